// round 5
// baseline (speedup 1.0000x reference)
#include <cuda_runtime.h>
#include <math.h>

#define HB   64
#define HDIM 131072
#define HN1  512
#define HN2  256
#define COLSTRIDE 1032   // 1024 + 8 pad (float2) to break bank conflicts across columns

// Static device scratch (allowed; no runtime allocation)
static __device__ float2 g_bufA[(size_t)HB * HDIM];   // 64 MB  stage-1 data (permuted)
static __device__ float2 g_bufP[(size_t)HB * HDIM];   // 64 MB  product P (permuted)
static __device__ float2 g_twN[HDIM];                 // W_N^t table, 1 MB
static __device__ unsigned g_maxbits;
static __device__ float2 g_gates[HB];                 // (store, retrieve) per row

__device__ __forceinline__ float2 cmulf(float2 a, float2 b) {
    return make_float2(fmaf(a.x, b.x, -a.y * b.y), fmaf(a.x, b.y, a.y * b.x));
}

// Warp-level radix-2 Stockham FFT of SIZE=2^LOG2S points, ping-pong inside s[0..2*SIZE).
// tw[i] = exp(-2*pi*i * i / 512), i in [0,256). Result lands at offset (LOG2S odd ? SIZE : 0),
// in natural order. Unscaled. INV => conjugated twiddles (inverse DFT without 1/N).
template<int LOG2S, bool INV>
__device__ __forceinline__ void warp_fft(float2* s, const float2* tw) {
    const int SIZE = 1 << LOG2S;
    const int lane = threadIdx.x & 31;
    int off_in = 0, off_out = SIZE;
#pragma unroll
    for (int st = 0; st < LOG2S; ++st) {
        const float2* src = s + off_in;
        float2* dst = s + off_out;
        const int m = 1 << st;
#pragma unroll
        for (int b = lane; b < (SIZE >> 1); b += 32) {
            int j = b >> st;                       // b = j*m + k
            float2 c0 = src[b];
            float2 c1 = src[b + (SIZE >> 1)];
            float2 w = tw[j << (st + 9 - LOG2S)];
            if (INV) w.y = -w.y;
            float2 d0 = make_float2(c0.x + c1.x, c0.y + c1.y);
            float2 d1 = make_float2(c0.x - c1.x, c0.y - c1.y);
            int o = b + j * m;                     // k + 2*j*m
            dst[o]     = d0;
            dst[o + m] = cmulf(w, d1);
        }
        __syncwarp();
        int t = off_in; off_in = off_out; off_out = t;
    }
}

// ---------------- setup kernels ----------------

// Gates + tail (dummy_ptr zeros + scalar 1.0) at fixed float position tail_pos.
__global__ void k_init(const float* __restrict__ ctrl, float* __restrict__ outf,
                       long long tail_pos, int tail_on) {
    int t = blockIdx.x * blockDim.x + threadIdx.x;
    if (t == 0) g_maxbits = 0u;
    if (t < HB) {
        float s = 1.f / (1.f + expf(-ctrl[t * 3 + 0]));
        float r = 1.f / (1.f + expf(-ctrl[t * 3 + 1]));
        g_gates[t] = make_float2(s, r);
    }
    if (tail_on && t < 65) outf[tail_pos + t] = (t == 64) ? 1.f : 0.f;
}

__global__ void k_tw() {
    int i = blockIdx.x * blockDim.x + threadIdx.x;
    double a = -2.0 * 3.14159265358979323846 * (double)i / (double)HDIM;
    g_twN[i] = make_float2((float)cos(a), (float)sin(a));
}

__global__ void k_max(const float* __restrict__ z, int n) {
    __shared__ float sm[8];
    float m = 0.f;
    for (int i = blockIdx.x * blockDim.x + threadIdx.x; i < n; i += gridDim.x * blockDim.x)
        m = fmaxf(m, fabsf(z[i]));
#pragma unroll
    for (int o = 16; o; o >>= 1) m = fmaxf(m, __shfl_xor_sync(0xffffffffu, m, o));
    if ((threadIdx.x & 31) == 0) sm[threadIdx.x >> 5] = m;
    __syncthreads();
    if (threadIdx.x < 8) {
        m = sm[threadIdx.x];
#pragma unroll
        for (int o = 4; o; o >>= 1) m = fmaxf(m, __shfl_xor_sync(0xffu, m, o));
        if (threadIdx.x == 0) atomicMax(&g_maxbits, __float_as_uint(m));
    }
}

// ---------------- four-step FFT ----------------
// x[n], n = n1*256 + n2.  Spectrum stored permuted: S[k1*256 + k2] = X[k1 + 512*k2].

extern __shared__ float2 smem[];

// Pass F1: per 8 columns n2, length-512 FFT over n1 (stride 256), apply W_N^{n2*k1}.
// Builds c = new_trace + i*z_norm and writes new_trace out (mode-dependent).
__global__ __launch_bounds__(256) void k_fwd1(const float* __restrict__ z,
                                              const float* __restrict__ tr,
                                              float* __restrict__ outf,
                                              float2* __restrict__ outc,
                                              int nt_mode) {
    float2* scol = smem;                    // 8 cols * COLSTRIDE
    float2* tw   = smem + 8 * COLSTRIDE;    // 256
    const int row = blockIdx.y;
    const int n2base = blockIdx.x * 8;
    const int tid = threadIdx.x;
    if (tid < 256) tw[tid] = g_twN[tid * 256];

    const float mx = __uint_as_float(g_maxbits);
    const float scale = 1.f / (mx + 1e-6f);
    const float st_g = g_gates[row].x;
    const size_t rb = (size_t)row * HDIM;
    const size_t BD = (size_t)HB * HDIM;

    for (int i = tid; i < 4096; i += 256) {
        int n1 = i >> 3, j = i & 7;
        size_t gidx = rb + (n1 << 8) + n2base + j;
        float zn  = z[gidx] * scale;
        float ntv = tr[gidx] + st_g * zn;
        scol[j * COLSTRIDE + n1] = make_float2(ntv, zn);
        if (nt_mode == 1)      outf[BD + gidx] = ntv;                    // real float
        else if (nt_mode == 2) outc[BD + gidx] = make_float2(ntv, 0.f);  // complex
    }
    __syncthreads();
    warp_fft<9, false>(scol + (tid >> 5) * COLSTRIDE, tw);       // result at +512
    __syncthreads();
    for (int i = tid; i < 4096; i += 256) {
        int k1 = i >> 3, j = i & 7;
        int n2 = n2base + j;
        float2 v = scol[j * COLSTRIDE + 512 + k1];
        float2 w = g_twN[(n2 * k1) & (HDIM - 1)];
        g_bufA[rb + (k1 << 8) + n2] = cmulf(v, w);
    }
}

// Pass F2+point fused: per block, 256-pt FFTs for 4 k1 values AND their mirrors 512-k1,
// then Hermitian split NT/Z from shared memory and write P = NT*conj(Z)*retr/N to bufP.
__global__ __launch_bounds__(256) void k_fwd2p() {
    const int w = threadIdx.x >> 5;
    const int lane = threadIdx.x & 31;
    float2* sb = smem + w * 512;            // per-warp 512 float2 (ping-pong for SIZE=256)
    float2* tw = smem + 8 * 512;            // 256
    const int row = blockIdx.y;
    const int bx = blockIdx.x;              // [0,64)
    int wlow = bx * 4 + (w & 3);            // [0,256)
    int k1 = (w < 4) ? wlow : ((512 - wlow) & 511);
    if (bx == 0 && w == 4) k1 = 256;        // replace duplicate of k1=0 with self-mirrored 256
    const int k1m = (512 - k1) & 511;
    const int pw = (k1m == k1) ? w : (w ^ 4);   // partner warp holding mirror spectrum
    if (threadIdx.x < 256) tw[threadIdx.x] = g_twN[threadIdx.x * 256];
    const size_t base = (size_t)row * HDIM + ((size_t)k1 << 8);
    for (int i = lane; i < 256; i += 32) sb[i] = g_bufA[base + i];
    __syncthreads();
    warp_fft<8, false>(sb, tw);             // result at +0
    __syncthreads();                        // cross-warp mirror reads below
    const float fac = g_gates[row].y * (1.f / (float)HDIM);
    const float2* sp = smem + pw * 512;
    for (int k2 = lane; k2 < 256; k2 += 32) {
        int k2m = (k1 == 0) ? ((256 - k2) & 255) : (255 - k2);
        float2 C  = sb[k2];
        float2 Cm = sp[k2m];                // C at wavenumber -k
        float2 NT = make_float2(0.5f * (C.x + Cm.x), 0.5f * (C.y - Cm.y));
        float2 Z  = make_float2(0.5f * (C.y + Cm.y), -0.5f * (C.x - Cm.x));
        float2 Zc = make_float2(Z.x, -Z.y);
        float2 P  = cmulf(NT, Zc);
        g_bufP[base + k2] = make_float2(P.x * fac, P.y * fac);
    }
}

// Pass I1: per k1, length-256 inverse FFT over k2 (contiguous), apply conj(W_N^{n2*k1}).
__global__ __launch_bounds__(256) void k_inv1() {
    float2* sb = smem + (threadIdx.x >> 5) * 512;
    float2* tw = smem + 8 * 512;
    const int row = blockIdx.y;
    const int k1 = blockIdx.x * 8 + (threadIdx.x >> 5);
    const int lane = threadIdx.x & 31;
    if (threadIdx.x < 256) tw[threadIdx.x] = g_twN[threadIdx.x * 256];
    const size_t base = (size_t)row * HDIM + (k1 << 8);
    for (int i = lane; i < 256; i += 32) sb[i] = g_bufP[base + i];
    __syncthreads();
    warp_fft<8, true>(sb, tw);              // result at +0
    for (int i = lane; i < 256; i += 32) {
        float2 w = g_twN[(i * k1) & (HDIM - 1)];
        w.y = -w.y;
        g_bufP[base + i] = cmulf(sb[i], w);
    }
}

// Pass I2: per 8 columns n2, length-512 inverse FFT over k1 (stride 256) -> read output.
// read_mode: 1 = interleaved float2, 2 = real part only (float per element).
__global__ __launch_bounds__(256) void k_inv2(float* __restrict__ outf,
                                              float2* __restrict__ outc, int read_mode) {
    float2* scol = smem;
    float2* tw   = smem + 8 * COLSTRIDE;
    const int row = blockIdx.y;
    const int n2base = blockIdx.x * 8;
    const int tid = threadIdx.x;
    if (tid < 256) tw[tid] = g_twN[tid * 256];
    const size_t rb = (size_t)row * HDIM;
    for (int i = tid; i < 4096; i += 256) {
        int k1 = i >> 3, j = i & 7;
        scol[j * COLSTRIDE + k1] = g_bufP[rb + (k1 << 8) + n2base + j];
    }
    __syncthreads();
    warp_fft<9, true>(scol + (tid >> 5) * COLSTRIDE, tw);        // result at +512
    __syncthreads();
    if (read_mode == 2) {
        for (int i = tid; i < 4096; i += 256) {
            int n1 = i >> 3, j = i & 7;
            outf[rb + (n1 << 8) + n2base + j] = scol[j * COLSTRIDE + 512 + n1].x;
        }
    } else if (read_mode == 1) {
        for (int i = tid; i < 4096; i += 256) {
            int n1 = i >> 3, j = i & 7;
            outc[rb + (n1 << 8) + n2base + j] = scol[j * COLSTRIDE + 512 + n1];
        }
    }
}

// ---------------- launcher ----------------

extern "C" void kernel_launch(void* const* d_in, const int* in_sizes, int n_in,
                              void* d_out, int out_size) {
    // Identify inputs strictly by size: two B*DIM arrays (z then trace_in, order
    // preserved) and one B*3 ctrl. If the contract doesn't hold, launch nothing.
    const float* big[2] = {nullptr, nullptr};
    const float* ctrl = nullptr;
    int nb = 0;
    for (int i = 0; i < n_in; ++i) {
        if (in_sizes[i] == HB * 3) ctrl = (const float*)d_in[i];
        else if (in_sizes[i] == HB * HDIM && nb < 2) big[nb++] = (const float*)d_in[i];
    }
    if (nb != 2 || !ctrl) return;
    const float* z  = big[0];
    const float* tr = big[1];

    // SAFETY: every output store lies within out_size*4 bytes (minimal element size),
    // valid under any actual dtype.
    const long long BD = (long long)HB * HDIM;   // 8,388,608
    long long os = out_size;
    int read_mode = 0, nt_mode = 0, tail_on = 0;
    long long tail_pos = 0;
    if (os >= 4 * BD) {              // complex-interleaved layout
        read_mode = 1; nt_mode = 2;
        tail_pos = 4 * BD; tail_on = (os >= 4 * BD + 65);
    } else if (os >= 2 * BD) {       // float32 real-part layout  (expected: os = 2BD+65)
        read_mode = 2; nt_mode = 1;
        tail_pos = 2 * BD; tail_on = (os >= 2 * BD + 65);
    } else if (os >= BD) {           // read.real only
        read_mode = 2;
    }

    float*  outf = (float*)d_out;
    float2* outc = (float2*)d_out;

    const int S1 = (8 * COLSTRIDE + 256) * (int)sizeof(float2);  // ~68 KB
    const int S2 = (8 * 512 + 256) * (int)sizeof(float2);        // ~34 KB
    cudaFuncSetAttribute(k_fwd1,  cudaFuncAttributeMaxDynamicSharedMemorySize, S1);
    cudaFuncSetAttribute(k_inv2,  cudaFuncAttributeMaxDynamicSharedMemorySize, S1);
    cudaFuncSetAttribute(k_fwd2p, cudaFuncAttributeMaxDynamicSharedMemorySize, S2);
    cudaFuncSetAttribute(k_inv1,  cudaFuncAttributeMaxDynamicSharedMemorySize, S2);

    k_init<<<1, 128>>>(ctrl, outf, tail_pos, tail_on);
    k_tw<<<HDIM / 256, 256>>>();
    k_max<<<1024, 256>>>(z, HB * HDIM);
    k_fwd1<<<dim3(HN2 / 8, HB), 256, S1>>>(z, tr, outf, outc, nt_mode);
    k_fwd2p<<<dim3(HN1 / 8, HB), 256, S2>>>();
    k_inv1<<<dim3(HN1 / 8, HB), 256, S2>>>();
    k_inv2<<<dim3(HN2 / 8, HB), 256, S1>>>(outf, outc, read_mode);
}

// round 6
// speedup vs baseline: 1.3580x; 1.3580x over previous
#include <cuda_runtime.h>
#include <math.h>

#define HB   64
#define HDIM 131072
#define HN1  512
#define HN2  256
#define CS   1154            // column stride (float2) for 512-FFT kernels: A[576] + B[576] + pad
#define MAP(i) ((i) + ((i) >> 3))   // padded intermediate layout (conflict reduction)

// Static device scratch (allowed; no runtime allocation)
static __device__ float2 g_bufA[(size_t)HB * HDIM];   // 64 MB  stage-1 data (permuted)
static __device__ float2 g_bufP[(size_t)HB * HDIM];   // 64 MB  product P (permuted)
static __device__ float2 g_twN[HDIM];                 // W_N^t table, 1 MB
static __device__ unsigned g_maxbits;
static __device__ float2 g_gates[HB];                 // (store, retrieve) per row

__device__ __forceinline__ float2 cmulf(float2 a, float2 b) {
    return make_float2(fmaf(a.x, b.x, -a.y * b.y), fmaf(a.x, b.y, a.y * b.x));
}
__device__ __forceinline__ float2 cadd(float2 a, float2 b) { return make_float2(a.x + b.x, a.y + b.y); }
__device__ __forceinline__ float2 csub(float2 a, float2 b) { return make_float2(a.x - b.x, a.y - b.y); }
template<bool INV> __device__ __forceinline__ float2 mulmi(float2 v) {   // *(−i) fwd, *(+i) inv
    return INV ? make_float2(-v.y, v.x) : make_float2(v.y, -v.x);
}

// 8-point DFT in registers, natural in/out order. d_r = sum_t c_t w8^{±rt}.
template<bool INV> __device__ __forceinline__ void dft8(float2* c) {
    const float s = 0.70710678118654752440f;
    float2 e0 = c[0], e1 = c[4], e2 = c[2], e3 = c[6], e4 = c[1], e5 = c[5], e6 = c[3], e7 = c[7];
    float2 f0 = cadd(e0, e1), f1 = csub(e0, e1), f2 = cadd(e2, e3), f3 = csub(e2, e3);
    float2 f4 = cadd(e4, e5), f5 = csub(e4, e5), f6 = cadd(e6, e7), f7 = csub(e6, e7);
    float2 t3 = mulmi<INV>(f3), t7 = mulmi<INV>(f7);
    float2 g0 = cadd(f0, f2), g2 = csub(f0, f2), g1 = cadd(f1, t3), g3 = csub(f1, t3);
    float2 g4 = cadd(f4, f6), g6 = csub(f4, f6), g5 = cadd(f5, t7), g7 = csub(f5, t7);
    float2 h5 = INV ? make_float2(s * (g5.x - g5.y), s * (g5.y + g5.x))
                    : make_float2(s * (g5.x + g5.y), s * (g5.y - g5.x));
    float2 h6 = mulmi<INV>(g6);
    float2 h7 = INV ? make_float2(-s * (g7.x + g7.y), -s * (g7.y - g7.x))
                    : make_float2(-s * (g7.x - g7.y), -s * (g7.x + g7.y));
    c[0] = cadd(g0, g4); c[4] = csub(g0, g4);
    c[1] = cadd(g1, h5); c[5] = csub(g1, h5);
    c[2] = cadd(g2, h6); c[6] = csub(g2, h6);
    c[3] = cadd(g3, h7); c[7] = csub(g3, h7);
}
template<bool INV> __device__ __forceinline__ void dft4(float2* c) {
    float2 a0 = cadd(c[0], c[2]), a1 = csub(c[0], c[2]);
    float2 a2 = cadd(c[1], c[3]), a3 = csub(c[1], c[3]);
    float2 t = mulmi<INV>(a3);
    c[0] = cadd(a0, a2); c[2] = csub(a0, a2); c[1] = cadd(a1, t); c[3] = csub(a1, t);
}
__device__ __forceinline__ void twpow8(float2* c, float2 w) {   // c[r] *= w^r
    float2 wr = w;
#pragma unroll
    for (int r = 1; r < 8; ++r) { c[r] = cmulf(c[r], wr); wr = cmulf(wr, w); }
}

// 512-point radix-8 Stockham FFT (3 stages) on one warp's column.
// A holds natural input; result lands in B natural order. tws[i]=exp(-2pi i i/512), i<64.
template<bool INV>
__device__ __forceinline__ void fft512_r8(float2* A, float2* B, const float2* tws, int lane) {
#pragma unroll 1
    for (int h = 0; h < 2; ++h) {            // stage 1: m=1, A(nat)->B(map)
        int b = lane + 32 * h;
        float2 c[8];
#pragma unroll
        for (int t = 0; t < 8; ++t) c[t] = A[b + 64 * t];
        dft8<INV>(c);
        float2 w = tws[b]; if (INV) w.y = -w.y;
        twpow8(c, w);
#pragma unroll
        for (int r = 0; r < 8; ++r) B[MAP(8 * b + r)] = c[r];
    }
    __syncwarp();
#pragma unroll 1
    for (int h = 0; h < 2; ++h) {            // stage 2: m=8, B(map)->A(map)
        int b = lane + 32 * h; int j = b >> 3, k = b & 7;
        float2 c[8];
#pragma unroll
        for (int t = 0; t < 8; ++t) c[t] = B[MAP(b + 64 * t)];
        dft8<INV>(c);
        float2 w = tws[8 * j]; if (INV) w.y = -w.y;
        twpow8(c, w);
#pragma unroll
        for (int r = 0; r < 8; ++r) A[MAP(k + 64 * j + 8 * r)] = c[r];
    }
    __syncwarp();
#pragma unroll 1
    for (int h = 0; h < 2; ++h) {            // stage 3: m=64, no twiddle, A(map)->B(nat)
        int b = lane + 32 * h;
        float2 c[8];
#pragma unroll
        for (int t = 0; t < 8; ++t) c[t] = A[MAP(b + 64 * t)];
        dft8<INV>(c);
#pragma unroll
        for (int r = 0; r < 8; ++r) B[b + 64 * r] = c[r];
    }
    __syncwarp();
}

// ---------------- setup kernels ----------------

__global__ void k_init(const float* __restrict__ ctrl, float* __restrict__ outf,
                       long long tail_pos, int tail_on) {
    int t = blockIdx.x * blockDim.x + threadIdx.x;
    if (t == 0) g_maxbits = 0u;
    if (t < HB) {
        float s = 1.f / (1.f + expf(-ctrl[t * 3 + 0]));
        float r = 1.f / (1.f + expf(-ctrl[t * 3 + 1]));
        g_gates[t] = make_float2(s, r);
    }
    if (tail_on && t < 65) outf[tail_pos + t] = (t == 64) ? 1.f : 0.f;
}

__global__ void k_tw() {
    int i = blockIdx.x * blockDim.x + threadIdx.x;
    double a = -2.0 * 3.14159265358979323846 * (double)i / (double)HDIM;
    g_twN[i] = make_float2((float)cos(a), (float)sin(a));
}

__global__ void k_max(const float* __restrict__ z, int n) {
    __shared__ float sm[8];
    float m = 0.f;
    for (int i = blockIdx.x * blockDim.x + threadIdx.x; i < n; i += gridDim.x * blockDim.x)
        m = fmaxf(m, fabsf(z[i]));
#pragma unroll
    for (int o = 16; o; o >>= 1) m = fmaxf(m, __shfl_xor_sync(0xffffffffu, m, o));
    if ((threadIdx.x & 31) == 0) sm[threadIdx.x >> 5] = m;
    __syncthreads();
    if (threadIdx.x < 8) {
        m = sm[threadIdx.x];
#pragma unroll
        for (int o = 4; o; o >>= 1) m = fmaxf(m, __shfl_xor_sync(0xffu, m, o));
        if (threadIdx.x == 0) atomicMax(&g_maxbits, __float_as_uint(m));
    }
}

// ---------------- FFT passes ----------------
// x[n], n = n1*256 + n2.  Spectrum stored permuted: S[k1*256 + k2] = X[k1 + 512*k2].

extern __shared__ float2 smem[];

// F1: per 8 columns n2, 512-FFT over n1 (radix-8), apply W_N^{n2*k1}, write bufA.
__global__ __launch_bounds__(256) void k_fwd1(const float* __restrict__ z,
                                              const float* __restrict__ tr,
                                              float* __restrict__ outf,
                                              float2* __restrict__ outc,
                                              int nt_mode) {
    const int w = threadIdx.x >> 5, lane = threadIdx.x & 31;
    float2* A = smem + w * CS;
    float2* B = A + 576;
    float2* tws = smem + 8 * CS;            // 64 entries
    if (threadIdx.x < 64) tws[threadIdx.x] = g_twN[threadIdx.x * 256];
    const int row = blockIdx.y;
    const int n2base = blockIdx.x * 8;
    const int tid = threadIdx.x;

    const float mx = __uint_as_float(g_maxbits);
    const float scale = 1.f / (mx + 1e-6f);
    const float st_g = g_gates[row].x;
    const size_t rb = (size_t)row * HDIM;
    const size_t BD = (size_t)HB * HDIM;

    for (int i = tid; i < 4096; i += 256) {
        int n1 = i >> 3, j = i & 7;
        size_t gidx = rb + (n1 << 8) + n2base + j;
        float zn  = z[gidx] * scale;
        float ntv = tr[gidx] + st_g * zn;
        smem[j * CS + n1] = make_float2(ntv, zn);
        if (nt_mode == 1)      outf[BD + gidx] = ntv;
        else if (nt_mode == 2) outc[BD + gidx] = make_float2(ntv, 0.f);
    }
    __syncthreads();
    fft512_r8<false>(A, B, tws, lane);      // result natural in B
    __syncthreads();
    for (int i = tid; i < 4096; i += 256) {
        int k1 = i >> 3, j = i & 7;
        int n2 = n2base + j;
        float2 v = smem[j * CS + 576 + k1];
        float2 tw4 = g_twN[(n2 * k1) & (HDIM - 1)];
        g_bufA[rb + (k1 << 8) + n2] = cmulf(v, tw4);
    }
}

// MID (fused fwd2 + Hermitian pointwise + inv1): per warp one k1 (and its mirror in a
// partner warp). Forward 256-FFT from global (coalesced), split, product, inverse
// 256-FFT, conj four-step twiddle, write bufP.
__global__ __launch_bounds__(256) void k_mid() {
    const int w = threadIdx.x >> 5, lane = threadIdx.x & 31;
    float2* X = smem + w * 576;             // 288 entries
    float2* Y = X + 288;                    // 288 entries
    float2* tws = smem + 8 * 576;           // 32 entries: exp(-2pi i i/256)
    if (threadIdx.x < 32) tws[threadIdx.x] = g_twN[threadIdx.x * 512];

    const int row = blockIdx.y, bx = blockIdx.x;
    int wlow = bx * 4 + (w & 3);
    int k1 = (w < 4) ? wlow : ((512 - wlow) & 511);
    if (bx == 0 && w == 4) k1 = 256;        // replace duplicate of k1=0 with self-mirrored 256
    const int k1m = (512 - k1) & 511;
    const int pw = (k1m == k1) ? w : (w ^ 4);
    const size_t base = (size_t)row * HDIM + ((size_t)k1 << 8);
    __syncthreads();                        // tws visible to all warps

    // ---- forward 256-FFT (8,8,4) ----
    {   // stage 1: m=1, global(coalesced) -> X(map)
        int b = lane;
        float2 c[8];
#pragma unroll
        for (int t = 0; t < 8; ++t) c[t] = g_bufA[base + b + 32 * t];
        dft8<false>(c);
        twpow8(c, tws[b]);
#pragma unroll
        for (int r = 0; r < 8; ++r) X[MAP(8 * b + r)] = c[r];
    }
    __syncwarp();
    {   // stage 2: m=8, X(map) -> Y(map)
        int b = lane, j = b >> 3, k = b & 7;
        float2 c[8];
#pragma unroll
        for (int t = 0; t < 8; ++t) c[t] = X[MAP(b + 32 * t)];
        dft8<false>(c);
        twpow8(c, tws[8 * j]);
#pragma unroll
        for (int r = 0; r < 8; ++r) Y[MAP(k + 64 * j + 8 * r)] = c[r];
    }
    __syncwarp();
#pragma unroll 1
    for (int h = 0; h < 2; ++h) {           // stage 3: radix-4, m=64, Y(map) -> X(nat)
        int b = lane + 32 * h;
        float2 c[4];
#pragma unroll
        for (int t = 0; t < 4; ++t) c[t] = Y[MAP(b + 64 * t)];
        dft4<false>(c);
#pragma unroll
        for (int r = 0; r < 4; ++r) X[b + 64 * r] = c[r];
    }
    __syncthreads();                        // all warps' spectra ready (X natural)

    // ---- Hermitian split + product into registers ----
    const float fac = g_gates[row].y * (1.f / (float)HDIM);
    const float2* Xp = smem + pw * 576;
    float2 p[8];
#pragma unroll
    for (int t = 0; t < 8; ++t) {
        int k2 = lane + 32 * t;
        int k2m = (k1 == 0) ? ((256 - k2) & 255) : (255 - k2);
        float2 C  = X[k2];
        float2 Cm = Xp[k2m];
        float2 NT = make_float2(0.5f * (C.x + Cm.x), 0.5f * (C.y - Cm.y));
        float2 Z  = make_float2(0.5f * (C.y + Cm.y), -0.5f * (C.x - Cm.x));
        float2 Zc = make_float2(Z.x, -Z.y);
        float2 P  = cmulf(NT, Zc);
        p[t] = make_float2(P.x * fac, P.y * fac);
    }

    // ---- inverse 256-FFT ----
    dft8<true>(p);                          // stage 1: m=1, regs -> Y(map)
    { float2 wv = tws[lane]; wv.y = -wv.y; twpow8(p, wv); }
#pragma unroll
    for (int r = 0; r < 8; ++r) Y[MAP(8 * lane + r)] = p[r];
    __syncthreads();                        // partners done reading X; Y ready
    {   // stage 2: m=8, Y(map) -> X(map)
        int b = lane, j = b >> 3, k = b & 7;
        float2 c[8];
#pragma unroll
        for (int t = 0; t < 8; ++t) c[t] = Y[MAP(b + 32 * t)];
        dft8<true>(c);
        float2 wv = tws[8 * j]; wv.y = -wv.y;
        twpow8(c, wv);
#pragma unroll
        for (int r = 0; r < 8; ++r) X[MAP(k + 64 * j + 8 * r)] = c[r];
    }
    __syncwarp();
#pragma unroll 1
    for (int h = 0; h < 2; ++h) {           // stage 3: radix-4 -> global with conj twiddle
        int b = lane + 32 * h;
        float2 c[4];
#pragma unroll
        for (int t = 0; t < 4; ++t) c[t] = X[MAP(b + 64 * t)];
        dft4<true>(c);
#pragma unroll
        for (int r = 0; r < 4; ++r) {
            int n2 = b + 64 * r;
            float2 wv = g_twN[(n2 * k1) & (HDIM - 1)]; wv.y = -wv.y;
            g_bufP[base + n2] = cmulf(c[r], wv);
        }
    }
}

// I2: per 8 columns n2, inverse 512-FFT over k1 (radix-8) -> read output.
__global__ __launch_bounds__(256) void k_inv2(float* __restrict__ outf,
                                              float2* __restrict__ outc, int read_mode) {
    const int w = threadIdx.x >> 5, lane = threadIdx.x & 31;
    float2* A = smem + w * CS;
    float2* B = A + 576;
    float2* tws = smem + 8 * CS;
    if (threadIdx.x < 64) tws[threadIdx.x] = g_twN[threadIdx.x * 256];
    const int row = blockIdx.y;
    const int n2base = blockIdx.x * 8;
    const int tid = threadIdx.x;
    const size_t rb = (size_t)row * HDIM;

    for (int i = tid; i < 4096; i += 256) {
        int k1 = i >> 3, j = i & 7;
        smem[j * CS + k1] = g_bufP[rb + (k1 << 8) + n2base + j];
    }
    __syncthreads();
    fft512_r8<true>(A, B, tws, lane);       // result natural in B
    __syncthreads();
    if (read_mode == 2) {
        for (int i = tid; i < 4096; i += 256) {
            int n1 = i >> 3, j = i & 7;
            outf[rb + (n1 << 8) + n2base + j] = smem[j * CS + 576 + n1].x;
        }
    } else if (read_mode == 1) {
        for (int i = tid; i < 4096; i += 256) {
            int n1 = i >> 3, j = i & 7;
            outc[rb + (n1 << 8) + n2base + j] = smem[j * CS + 576 + n1];
        }
    }
}

// ---------------- launcher ----------------

extern "C" void kernel_launch(void* const* d_in, const int* in_sizes, int n_in,
                              void* d_out, int out_size) {
    const float* big[2] = {nullptr, nullptr};
    const float* ctrl = nullptr;
    int nb = 0;
    for (int i = 0; i < n_in; ++i) {
        if (in_sizes[i] == HB * 3) ctrl = (const float*)d_in[i];
        else if (in_sizes[i] == HB * HDIM && nb < 2) big[nb++] = (const float*)d_in[i];
    }
    if (nb != 2 || !ctrl) return;
    const float* z  = big[0];
    const float* tr = big[1];

    // SAFETY: every output store lies within out_size*4 bytes (minimal element size).
    const long long BD = (long long)HB * HDIM;
    long long os = out_size;
    int read_mode = 0, nt_mode = 0, tail_on = 0;
    long long tail_pos = 0;
    if (os >= 4 * BD) {              // complex-interleaved layout
        read_mode = 1; nt_mode = 2;
        tail_pos = 4 * BD; tail_on = (os >= 4 * BD + 65);
    } else if (os >= 2 * BD) {       // float32 real-part layout (os = 2BD+65)
        read_mode = 2; nt_mode = 1;
        tail_pos = 2 * BD; tail_on = (os >= 2 * BD + 65);
    } else if (os >= BD) {
        read_mode = 2;
    }

    float*  outf = (float*)d_out;
    float2* outc = (float2*)d_out;

    const int S1 = (8 * CS + 64) * (int)sizeof(float2);     // ~72.6 KB
    const int SM = (8 * 576 + 32) * (int)sizeof(float2);    // ~36.3 KB
    cudaFuncSetAttribute(k_fwd1, cudaFuncAttributeMaxDynamicSharedMemorySize, S1);
    cudaFuncSetAttribute(k_inv2, cudaFuncAttributeMaxDynamicSharedMemorySize, S1);
    cudaFuncSetAttribute(k_mid,  cudaFuncAttributeMaxDynamicSharedMemorySize, SM);

    k_init<<<1, 128>>>(ctrl, outf, tail_pos, tail_on);
    k_tw<<<HDIM / 256, 256>>>();
    k_max<<<1024, 256>>>(z, HB * HDIM);
    k_fwd1<<<dim3(HN2 / 8, HB), 256, S1>>>(z, tr, outf, outc, nt_mode);
    k_mid<<<dim3(HN1 / 8, HB), 256, SM>>>();
    k_inv2<<<dim3(HN2 / 8, HB), 256, S1>>>(outf, outc, read_mode);
}

// round 7
// speedup vs baseline: 1.7265x; 1.2713x over previous
#include <cuda_runtime.h>
#include <math.h>

#define HB   64
#define HDIM 131072
#define HN1  512
#define HN2  256
#define CS   1154            // column stride (float2) for 512-FFT kernels: A[576] + B[576] + pad
#define MAP(i) ((i) + ((i) >> 3))   // padded intermediate layout (conflict reduction)

// Static device scratch (allowed; no runtime allocation)
static __device__ float2 g_bufA[(size_t)HB * HDIM];   // 64 MB  stage-1 data (permuted)
static __device__ float2 g_bufP[(size_t)HB * HDIM];   // 64 MB  product P (permuted)
static __device__ float2 g_twN[HDIM];                 // W_N^t table, 1 MB
static __device__ unsigned g_maxbits;
static __device__ float2 g_gates[HB];                 // (store, retrieve) per row

__device__ __forceinline__ float2 cmulf(float2 a, float2 b) {
    return make_float2(fmaf(a.x, b.x, -a.y * b.y), fmaf(a.x, b.y, a.y * b.x));
}
__device__ __forceinline__ float2 cadd(float2 a, float2 b) { return make_float2(a.x + b.x, a.y + b.y); }
__device__ __forceinline__ float2 csub(float2 a, float2 b) { return make_float2(a.x - b.x, a.y - b.y); }
template<bool INV> __device__ __forceinline__ float2 mulmi(float2 v) {   // *(−i) fwd, *(+i) inv
    return INV ? make_float2(-v.y, v.x) : make_float2(v.y, -v.x);
}

// 8-point DFT in registers, natural in/out order.
template<bool INV> __device__ __forceinline__ void dft8(float2* c) {
    const float s = 0.70710678118654752440f;
    float2 e0 = c[0], e1 = c[4], e2 = c[2], e3 = c[6], e4 = c[1], e5 = c[5], e6 = c[3], e7 = c[7];
    float2 f0 = cadd(e0, e1), f1 = csub(e0, e1), f2 = cadd(e2, e3), f3 = csub(e2, e3);
    float2 f4 = cadd(e4, e5), f5 = csub(e4, e5), f6 = cadd(e6, e7), f7 = csub(e6, e7);
    float2 t3 = mulmi<INV>(f3), t7 = mulmi<INV>(f7);
    float2 g0 = cadd(f0, f2), g2 = csub(f0, f2), g1 = cadd(f1, t3), g3 = csub(f1, t3);
    float2 g4 = cadd(f4, f6), g6 = csub(f4, f6), g5 = cadd(f5, t7), g7 = csub(f5, t7);
    float2 h5 = INV ? make_float2(s * (g5.x - g5.y), s * (g5.y + g5.x))
                    : make_float2(s * (g5.x + g5.y), s * (g5.y - g5.x));
    float2 h6 = mulmi<INV>(g6);
    float2 h7 = INV ? make_float2(-s * (g7.x + g7.y), -s * (g7.y - g7.x))
                    : make_float2(-s * (g7.x - g7.y), -s * (g7.x + g7.y));
    c[0] = cadd(g0, g4); c[4] = csub(g0, g4);
    c[1] = cadd(g1, h5); c[5] = csub(g1, h5);
    c[2] = cadd(g2, h6); c[6] = csub(g2, h6);
    c[3] = cadd(g3, h7); c[7] = csub(g3, h7);
}
template<bool INV> __device__ __forceinline__ void dft4(float2* c) {
    float2 a0 = cadd(c[0], c[2]), a1 = csub(c[0], c[2]);
    float2 a2 = cadd(c[1], c[3]), a3 = csub(c[1], c[3]);
    float2 t = mulmi<INV>(a3);
    c[0] = cadd(a0, a2); c[2] = csub(a0, a2); c[1] = cadd(a1, t); c[3] = csub(a1, t);
}
__device__ __forceinline__ void twpow8(float2* c, float2 w) {   // c[r] *= w^r
    float2 wr = w;
#pragma unroll
    for (int r = 1; r < 8; ++r) { c[r] = cmulf(c[r], wr); wr = cmulf(wr, w); }
}

// 512-point radix-8 Stockham FFT, 64 butterflies/stage split across 2 warps
// (bb in [0,64)). Cross-warp stage sync = __syncthreads (all columns in lockstep).
// A natural input; result natural in B. tws[i]=exp(-2pi i i/512), i<64.
template<bool INV>
__device__ __forceinline__ void fft512_r8(float2* A, float2* B, const float2* tws, int bb) {
    {   // stage 1: m=1, A(nat)->B(map)
        float2 c[8];
#pragma unroll
        for (int t = 0; t < 8; ++t) c[t] = A[bb + 64 * t];
        dft8<INV>(c);
        float2 w = tws[bb]; if (INV) w.y = -w.y;
        twpow8(c, w);
#pragma unroll
        for (int r = 0; r < 8; ++r) B[MAP(8 * bb + r)] = c[r];
    }
    __syncthreads();
    {   // stage 2: m=8, B(map)->A(map)
        int j = bb >> 3, k = bb & 7;
        float2 c[8];
#pragma unroll
        for (int t = 0; t < 8; ++t) c[t] = B[MAP(bb + 64 * t)];
        dft8<INV>(c);
        float2 w = tws[8 * j]; if (INV) w.y = -w.y;
        twpow8(c, w);
#pragma unroll
        for (int r = 0; r < 8; ++r) A[MAP(k + 64 * j + 8 * r)] = c[r];
    }
    __syncthreads();
    {   // stage 3: m=64, no twiddle, A(map)->B(nat)
        float2 c[8];
#pragma unroll
        for (int t = 0; t < 8; ++t) c[t] = A[MAP(bb + 64 * t)];
        dft8<INV>(c);
#pragma unroll
        for (int r = 0; r < 8; ++r) B[bb + 64 * r] = c[r];
    }
    __syncthreads();
}

// ---------------- setup kernels ----------------

__global__ void k_init(const float* __restrict__ ctrl, float* __restrict__ outf,
                       long long tail_pos, int tail_on) {
    int t = blockIdx.x * blockDim.x + threadIdx.x;
    if (t == 0) g_maxbits = 0u;
    if (t < HB) {
        float s = 1.f / (1.f + expf(-ctrl[t * 3 + 0]));
        float r = 1.f / (1.f + expf(-ctrl[t * 3 + 1]));
        g_gates[t] = make_float2(s, r);
    }
    if (tail_on && t < 65) outf[tail_pos + t] = (t == 64) ? 1.f : 0.f;
}

__global__ void k_tw() {
    int i = blockIdx.x * blockDim.x + threadIdx.x;
    // angle fraction 2*i/HDIM = i/65536 is exact in float (i < 2^17)
    float x = (float)i * (1.0f / 65536.0f);
    float s, c;
    sincospif(x, &s, &c);
    g_twN[i] = make_float2(c, -s);
}

__global__ void k_max(const float4* __restrict__ z4, int n4) {
    __shared__ float sm[8];
    float m = 0.f;
    for (int i = blockIdx.x * blockDim.x + threadIdx.x; i < n4; i += gridDim.x * blockDim.x) {
        float4 v = z4[i];
        m = fmaxf(m, fmaxf(fmaxf(fabsf(v.x), fabsf(v.y)), fmaxf(fabsf(v.z), fabsf(v.w))));
    }
#pragma unroll
    for (int o = 16; o; o >>= 1) m = fmaxf(m, __shfl_xor_sync(0xffffffffu, m, o));
    if ((threadIdx.x & 31) == 0) sm[threadIdx.x >> 5] = m;
    __syncthreads();
    if (threadIdx.x < 8) {
        m = sm[threadIdx.x];
#pragma unroll
        for (int o = 4; o; o >>= 1) m = fmaxf(m, __shfl_xor_sync(0xffu, m, o));
        if (threadIdx.x == 0) atomicMax(&g_maxbits, __float_as_uint(m));
    }
}

// ---------------- FFT passes ----------------
// x[n], n = n1*256 + n2.  Spectrum stored permuted: S[k1*256 + k2] = X[k1 + 512*k2].

extern __shared__ float2 smem[];

// F1 (512 threads): per 8 columns n2, 512-FFT over n1, apply W_N^{n2*k1}, write bufA.
__global__ __launch_bounds__(512) void k_fwd1(const float* __restrict__ z,
                                              const float* __restrict__ tr,
                                              float* __restrict__ outf,
                                              float2* __restrict__ outc,
                                              int nt_mode) {
    const int w = threadIdx.x >> 5, lane = threadIdx.x & 31;
    const int col = w >> 1;                 // column 0..7, 2 warps per column
    const int bb = lane + 32 * (w & 1);     // butterfly index 0..63
    float2* A = smem + col * CS;
    float2* B = A + 576;
    float2* tws = smem + 8 * CS;            // 64 entries
    if (threadIdx.x < 64) tws[threadIdx.x] = g_twN[threadIdx.x * 256];
    const int row = blockIdx.y;
    const int n2base = blockIdx.x * 8;
    const int tid = threadIdx.x;

    const float mx = __uint_as_float(g_maxbits);
    const float scale = 1.f / (mx + 1e-6f);
    const float st_g = g_gates[row].x;
    const size_t rb = (size_t)row * HDIM;
    const size_t BD = (size_t)HB * HDIM;

    for (int i = tid; i < 4096; i += 512) {
        int n1 = i >> 3, j = i & 7;
        size_t gidx = rb + (n1 << 8) + n2base + j;
        float zn  = z[gidx] * scale;
        float ntv = tr[gidx] + st_g * zn;
        smem[j * CS + n1] = make_float2(ntv, zn);
        if (nt_mode == 1)      outf[BD + gidx] = ntv;
        else if (nt_mode == 2) outc[BD + gidx] = make_float2(ntv, 0.f);
    }
    __syncthreads();
    fft512_r8<false>(A, B, tws, bb);        // result natural in B
    for (int i = tid; i < 4096; i += 512) {
        int k1 = i >> 3, j = i & 7;
        int n2 = n2base + j;
        float2 v = smem[j * CS + 576 + k1];
        float2 tw4 = g_twN[(n2 * k1) & (HDIM - 1)];
        g_bufA[rb + (k1 << 8) + n2] = cmulf(v, tw4);
    }
}

// MID (fused fwd2 + Hermitian pointwise + inv1), 256 threads, 1 warp per k1.
__global__ __launch_bounds__(256) void k_mid() {
    const int w = threadIdx.x >> 5, lane = threadIdx.x & 31;
    float2* X = smem + w * 576;             // 288 entries
    float2* Y = X + 288;                    // 288 entries
    float2* tws = smem + 8 * 576;           // 32 entries: exp(-2pi i i/256)
    if (threadIdx.x < 32) tws[threadIdx.x] = g_twN[threadIdx.x * 512];

    const int row = blockIdx.y, bx = blockIdx.x;
    int wlow = bx * 4 + (w & 3);
    int k1 = (w < 4) ? wlow : ((512 - wlow) & 511);
    if (bx == 0 && w == 4) k1 = 256;        // replace duplicate of k1=0 with self-mirrored 256
    const int k1m = (512 - k1) & 511;
    const int pw = (k1m == k1) ? w : (w ^ 4);
    const size_t base = (size_t)row * HDIM + ((size_t)k1 << 8);
    __syncthreads();                        // tws visible to all warps

    // ---- forward 256-FFT (8,8,4) ----
    {   // stage 1: m=1, global(coalesced) -> X(map)
        int b = lane;
        float2 c[8];
#pragma unroll
        for (int t = 0; t < 8; ++t) c[t] = g_bufA[base + b + 32 * t];
        dft8<false>(c);
        twpow8(c, tws[b]);
#pragma unroll
        for (int r = 0; r < 8; ++r) X[MAP(8 * b + r)] = c[r];
    }
    __syncwarp();
    {   // stage 2: m=8, X(map) -> Y(map)
        int b = lane, j = b >> 3, k = b & 7;
        float2 c[8];
#pragma unroll
        for (int t = 0; t < 8; ++t) c[t] = X[MAP(b + 32 * t)];
        dft8<false>(c);
        twpow8(c, tws[8 * j]);
#pragma unroll
        for (int r = 0; r < 8; ++r) Y[MAP(k + 64 * j + 8 * r)] = c[r];
    }
    __syncwarp();
#pragma unroll 1
    for (int h = 0; h < 2; ++h) {           // stage 3: radix-4, m=64, Y(map) -> X(nat)
        int b = lane + 32 * h;
        float2 c[4];
#pragma unroll
        for (int t = 0; t < 4; ++t) c[t] = Y[MAP(b + 64 * t)];
        dft4<false>(c);
#pragma unroll
        for (int r = 0; r < 4; ++r) X[b + 64 * r] = c[r];
    }
    __syncthreads();                        // all warps' spectra ready (X natural)

    // ---- Hermitian split + product into registers ----
    const float fac = g_gates[row].y * (1.f / (float)HDIM);
    const float2* Xp = smem + pw * 576;
    float2 p[8];
#pragma unroll
    for (int t = 0; t < 8; ++t) {
        int k2 = lane + 32 * t;
        int k2m = (k1 == 0) ? ((256 - k2) & 255) : (255 - k2);
        float2 C  = X[k2];
        float2 Cm = Xp[k2m];
        float2 NT = make_float2(0.5f * (C.x + Cm.x), 0.5f * (C.y - Cm.y));
        float2 Z  = make_float2(0.5f * (C.y + Cm.y), -0.5f * (C.x - Cm.x));
        float2 Zc = make_float2(Z.x, -Z.y);
        float2 P  = cmulf(NT, Zc);
        p[t] = make_float2(P.x * fac, P.y * fac);
    }

    // ---- inverse 256-FFT ----
    dft8<true>(p);                          // stage 1: m=1, regs -> Y(map)
    { float2 wv = tws[lane]; wv.y = -wv.y; twpow8(p, wv); }
#pragma unroll
    for (int r = 0; r < 8; ++r) Y[MAP(8 * lane + r)] = p[r];
    __syncthreads();                        // partners done reading X; Y ready
    {   // stage 2: m=8, Y(map) -> X(map)
        int b = lane, j = b >> 3, k = b & 7;
        float2 c[8];
#pragma unroll
        for (int t = 0; t < 8; ++t) c[t] = Y[MAP(b + 32 * t)];
        dft8<true>(c);
        float2 wv = tws[8 * j]; wv.y = -wv.y;
        twpow8(c, wv);
#pragma unroll
        for (int r = 0; r < 8; ++r) X[MAP(k + 64 * j + 8 * r)] = c[r];
    }
    __syncwarp();
#pragma unroll 1
    for (int h = 0; h < 2; ++h) {           // stage 3: radix-4 -> global with conj twiddle
        int b = lane + 32 * h;
        float2 c[4];
#pragma unroll
        for (int t = 0; t < 4; ++t) c[t] = X[MAP(b + 64 * t)];
        dft4<true>(c);
#pragma unroll
        for (int r = 0; r < 4; ++r) {
            int n2 = b + 64 * r;
            float2 wv = g_twN[(n2 * k1) & (HDIM - 1)]; wv.y = -wv.y;
            g_bufP[base + n2] = cmulf(c[r], wv);
        }
    }
}

// I2 (512 threads): per 8 columns n2, inverse 512-FFT over k1 -> read output.
__global__ __launch_bounds__(512) void k_inv2(float* __restrict__ outf,
                                              float2* __restrict__ outc, int read_mode) {
    const int w = threadIdx.x >> 5, lane = threadIdx.x & 31;
    const int col = w >> 1;
    const int bb = lane + 32 * (w & 1);
    float2* A = smem + col * CS;
    float2* B = A + 576;
    float2* tws = smem + 8 * CS;
    if (threadIdx.x < 64) tws[threadIdx.x] = g_twN[threadIdx.x * 256];
    const int row = blockIdx.y;
    const int n2base = blockIdx.x * 8;
    const int tid = threadIdx.x;
    const size_t rb = (size_t)row * HDIM;

    for (int i = tid; i < 4096; i += 512) {
        int k1 = i >> 3, j = i & 7;
        smem[j * CS + k1] = g_bufP[rb + (k1 << 8) + n2base + j];
    }
    __syncthreads();
    fft512_r8<true>(A, B, tws, bb);         // result natural in B
    if (read_mode == 2) {
        for (int i = tid; i < 4096; i += 512) {
            int n1 = i >> 3, j = i & 7;
            outf[rb + (n1 << 8) + n2base + j] = smem[j * CS + 576 + n1].x;
        }
    } else if (read_mode == 1) {
        for (int i = tid; i < 4096; i += 512) {
            int n1 = i >> 3, j = i & 7;
            outc[rb + (n1 << 8) + n2base + j] = smem[j * CS + 576 + n1];
        }
    }
}

// ---------------- launcher ----------------

extern "C" void kernel_launch(void* const* d_in, const int* in_sizes, int n_in,
                              void* d_out, int out_size) {
    const float* big[2] = {nullptr, nullptr};
    const float* ctrl = nullptr;
    int nb = 0;
    for (int i = 0; i < n_in; ++i) {
        if (in_sizes[i] == HB * 3) ctrl = (const float*)d_in[i];
        else if (in_sizes[i] == HB * HDIM && nb < 2) big[nb++] = (const float*)d_in[i];
    }
    if (nb != 2 || !ctrl) return;
    const float* z  = big[0];
    const float* tr = big[1];

    // SAFETY: every output store lies within out_size*4 bytes (minimal element size).
    const long long BD = (long long)HB * HDIM;
    long long os = out_size;
    int read_mode = 0, nt_mode = 0, tail_on = 0;
    long long tail_pos = 0;
    if (os >= 4 * BD) {              // complex-interleaved layout
        read_mode = 1; nt_mode = 2;
        tail_pos = 4 * BD; tail_on = (os >= 4 * BD + 65);
    } else if (os >= 2 * BD) {       // float32 real-part layout (os = 2BD+65)
        read_mode = 2; nt_mode = 1;
        tail_pos = 2 * BD; tail_on = (os >= 2 * BD + 65);
    } else if (os >= BD) {
        read_mode = 2;
    }

    float*  outf = (float*)d_out;
    float2* outc = (float2*)d_out;

    const int S1 = (8 * CS + 64) * (int)sizeof(float2);     // ~72.6 KB
    const int SM = (8 * 576 + 32) * (int)sizeof(float2);    // ~36.3 KB
    cudaFuncSetAttribute(k_fwd1, cudaFuncAttributeMaxDynamicSharedMemorySize, S1);
    cudaFuncSetAttribute(k_inv2, cudaFuncAttributeMaxDynamicSharedMemorySize, S1);
    cudaFuncSetAttribute(k_mid,  cudaFuncAttributeMaxDynamicSharedMemorySize, SM);

    k_init<<<1, 128>>>(ctrl, outf, tail_pos, tail_on);
    k_tw<<<HDIM / 256, 256>>>();
    k_max<<<1024, 256>>>((const float4*)z, (HB * HDIM) / 4);
    k_fwd1<<<dim3(HN2 / 8, HB), 512, S1>>>(z, tr, outf, outc, nt_mode);
    k_mid<<<dim3(HN1 / 8, HB), 256, SM>>>();
    k_inv2<<<dim3(HN2 / 8, HB), 512, S1>>>(outf, outc, read_mode);
}